// round 1
// baseline (speedup 1.0000x reference)
#include <cuda_runtime.h>

// Batched NT-GEMM: C[b,i,j] = sum_d A[b,i,d] * B[b,j,d]
// B=8, M=N=4096, K=128 (fp32).
// Classic SMEM-tiled SGEMM: BM=BN=128, BK=8, 256 threads, 8x8 per thread.

#define BATCH 8
#define MDIM 4096
#define NDIM 4096
#define KDIM 128

#define BM 128
#define BN 128
#define BK 8
#define TM 8
#define TN 8

__global__ __launch_bounds__(256, 2)
void sgemm_nt_kernel(const float* __restrict__ A,
                     const float* __restrict__ B,
                     float* __restrict__ C) {
    __shared__ float As[BK][BM];
    __shared__ float Bs[BK][BN];

    const int b = blockIdx.z;
    const float* Ab = A + (size_t)b * MDIM * KDIM;
    const float* Bb = B + (size_t)b * NDIM * KDIM;
    float* Cb = C + (size_t)b * MDIM * NDIM;

    const int tid = threadIdx.x;                 // 0..255
    // Global-load mapping: 128 rows x 8 cols per tile = 256 float4 loads? No:
    // 128 rows x 8 floats = 1024 floats = 256 float4 -> each thread loads 1 float4
    const int loadRow = tid >> 1;                // 0..127
    const int loadCol = (tid & 1) << 2;          // 0 or 4

    // Compute mapping: 16x16 thread grid of 8x8 micro-tiles
    const int tx = tid & 15;                     // n direction
    const int ty = tid >> 4;                     // m direction

    const int mBase = blockIdx.y * BM;
    const int nBase = blockIdx.x * BN;

    float acc[TM][TN];
    #pragma unroll
    for (int i = 0; i < TM; i++)
        #pragma unroll
        for (int j = 0; j < TN; j++)
            acc[i][j] = 0.0f;

    const float* aPtr = Ab + (size_t)(mBase + loadRow) * KDIM + loadCol;
    const float* bPtr = Bb + (size_t)(nBase + loadRow) * KDIM + loadCol;

    #pragma unroll 1
    for (int k0 = 0; k0 < KDIM; k0 += BK) {
        // Load A tile (BM x BK) and B tile (BN x BK), transpose into smem [BK][BM]
        float4 a4 = *reinterpret_cast<const float4*>(aPtr + k0);
        float4 b4 = *reinterpret_cast<const float4*>(bPtr + k0);

        As[loadCol + 0][loadRow] = a4.x;
        As[loadCol + 1][loadRow] = a4.y;
        As[loadCol + 2][loadRow] = a4.z;
        As[loadCol + 3][loadRow] = a4.w;

        Bs[loadCol + 0][loadRow] = b4.x;
        Bs[loadCol + 1][loadRow] = b4.y;
        Bs[loadCol + 2][loadRow] = b4.z;
        Bs[loadCol + 3][loadRow] = b4.w;

        __syncthreads();

        #pragma unroll
        for (int k = 0; k < BK; k++) {
            float ar[TM], br[TN];
            // vectorized smem reads
            *reinterpret_cast<float4*>(&ar[0]) =
                *reinterpret_cast<const float4*>(&As[k][ty * TM]);
            *reinterpret_cast<float4*>(&ar[4]) =
                *reinterpret_cast<const float4*>(&As[k][ty * TM + 4]);
            *reinterpret_cast<float4*>(&br[0]) =
                *reinterpret_cast<const float4*>(&Bs[k][tx * TN]);
            *reinterpret_cast<float4*>(&br[4]) =
                *reinterpret_cast<const float4*>(&Bs[k][tx * TN + 4]);

            #pragma unroll
            for (int i = 0; i < TM; i++)
                #pragma unroll
                for (int j = 0; j < TN; j++)
                    acc[i][j] = fmaf(ar[i], br[j], acc[i][j]);
        }

        __syncthreads();
    }

    // Write 8x8 result with float4 stores
    const int cm = mBase + ty * TM;
    const int cn = nBase + tx * TN;
    #pragma unroll
    for (int i = 0; i < TM; i++) {
        float* crow = Cb + (size_t)(cm + i) * NDIM + cn;
        *reinterpret_cast<float4*>(crow)     = *reinterpret_cast<float4*>(&acc[i][0]);
        *reinterpret_cast<float4*>(crow + 4) = *reinterpret_cast<float4*>(&acc[i][4]);
    }
}

extern "C" void kernel_launch(void* const* d_in, const int* in_sizes, int n_in,
                              void* d_out, int out_size) {
    const float* A = (const float*)d_in[0];
    const float* B = (const float*)d_in[1];
    float* C = (float*)d_out;

    dim3 grid(NDIM / BN, MDIM / BM, BATCH);   // 32 x 32 x 8 = 8192 CTAs
    dim3 block(256);
    sgemm_nt_kernel<<<grid, block>>>(A, B, C);
}

// round 4
// speedup vs baseline: 1.4501x; 1.4501x over previous
#include <cuda_runtime.h>
#include <cstdint>

// Batched NT-GEMM: C[b,i,j] = sum_d A[b,i,d] * B[b,j,d]
// B=8, M=N=4096, K=128, fp32 in/out.
// mma.sync.m16n8k8 tf32 path (arch-neutral PTX; harness targets sm_103 base,
// so tcgen05/'a'-features are unavailable).
//
// Per CTA: 128x128 tile, full K=128 in SMEM (fragment-major permuted layout),
// 8 warps each computing 64x32 via 4x4 grid of m16n8k8 tiles, 16 K-steps.

#define BATCH 8
#define MDIM 4096
#define NDIM 4096
#define KDIM 128

#define TILE_M 128
#define TILE_N 128

// SMEM: A fragments 64KB, B fragments 64KB.
// A_sm[mt(8)][kt(16)][lane(32)][r(4)] floats
// B_sm[nt(16)][kt(16)][lane(32)][r(2)] floats
#define SMEM_A 0
#define SMEM_B (64 * 1024)
#define SMEM_BYTES (128 * 1024)

__device__ __forceinline__ uint32_t f2tf32(float f) {
    uint32_t u;
    asm("cvt.rna.tf32.f32 %0, %1;" : "=r"(u) : "f"(f));
    return u;
}

__global__ __launch_bounds__(256, 1)
void bmm_tf32_mma_kernel(const float* __restrict__ A,
                         const float* __restrict__ B,
                         float* __restrict__ C) {
    extern __shared__ uint32_t smem[];
    uint32_t* A_sm = smem + SMEM_A / 4;
    uint32_t* B_sm = smem + SMEM_B / 4;

    const int tid  = threadIdx.x;
    const int lane = tid & 31;
    const int wid  = tid >> 5;

    const int b = blockIdx.z;
    const int mBase = blockIdx.y * TILE_M;
    const int nBase = blockIdx.x * TILE_N;

    const float* Ab = A + (size_t)b * MDIM * KDIM + (size_t)mBase * KDIM;
    const float* Bb = B + (size_t)b * NDIM * KDIM + (size_t)nBase * KDIM;
    float* Cb = C + (size_t)b * MDIM * NDIM;

    // ---- Load phase: global -> fragment-major SMEM, fp32 -> tf32 (RNA) ----
    // 128 rows x 32 float4 per tile = 4096 float4; 256 threads x 16 iters.
    #pragma unroll
    for (int t = 0; t < 16; t++) {
        const int idx = t * 256 + tid;
        const int row = idx >> 5;          // 0..127 (m for A, n for B)
        const int c4  = idx & 31;          // float4 index within row
        const int k0  = c4 * 4;

        float4 a4 = *reinterpret_cast<const float4*>(Ab + (size_t)row * KDIM + k0);
        float4 b4 = *reinterpret_cast<const float4*>(Bb + (size_t)row * KDIM + k0);

        // A dest: mt=row>>4, g=(row&15)&7, rhalf=(row&15)>>3
        //         kt=k>>3, tt=k&3, khalf=(k>>2)&1; lane=g*4+tt; r=rhalf+2*khalf
        {
            const int mt = row >> 4;
            const int g  = row & 7;
            const int rhalf = (row >> 3) & 1;
            const int kt = k0 >> 3;
            const int khalf = (k0 >> 2) & 1;    // same for all 4 elems
            const int r = rhalf + 2 * khalf;
            uint32_t* base = A_sm + ((mt * 16 + kt) * 32 + g * 4) * 4 + r;
            base[0 * 4] = f2tf32(a4.x);
            base[1 * 4] = f2tf32(a4.y);
            base[2 * 4] = f2tf32(a4.z);
            base[3 * 4] = f2tf32(a4.w);
        }
        // B dest: nt=row>>3, g=row&7; kt=k>>3, tt=k&3, r=(k>>2)&1; lane=g*4+tt
        {
            const int nt = row >> 3;
            const int g  = row & 7;
            const int kt = k0 >> 3;
            const int r  = (k0 >> 2) & 1;
            uint32_t* base = B_sm + ((nt * 16 + kt) * 32 + g * 4) * 2 + r;
            base[0 * 2] = f2tf32(b4.x);
            base[1 * 2] = f2tf32(b4.y);
            base[2 * 2] = f2tf32(b4.z);
            base[3 * 2] = f2tf32(b4.w);
        }
    }
    __syncthreads();

    // ---- Compute: warp wid -> m-band (wid>>2)*64, n-band (wid&3)*32 ----
    const int mband = wid >> 2;    // 0..1
    const int nband = wid & 3;     // 0..3

    float acc[4][4][4];
    #pragma unroll
    for (int i = 0; i < 4; i++)
        #pragma unroll
        for (int j = 0; j < 4; j++)
            #pragma unroll
            for (int r = 0; r < 4; r++)
                acc[i][j][r] = 0.0f;

    #pragma unroll
    for (int kt = 0; kt < 16; kt++) {
        uint32_t a[4][4];
        uint32_t bb[4][2];
        #pragma unroll
        for (int i = 0; i < 4; i++) {
            const uint32_t* p =
                A_sm + (((mband * 4 + i) * 16 + kt) * 32 + lane) * 4;
            asm volatile("ld.shared.v4.b32 {%0,%1,%2,%3}, [%4];"
                         : "=r"(a[i][0]), "=r"(a[i][1]),
                           "=r"(a[i][2]), "=r"(a[i][3])
                         : "l"(p));
        }
        #pragma unroll
        for (int j = 0; j < 4; j++) {
            const uint32_t* p =
                B_sm + (((nband * 4 + j) * 16 + kt) * 32 + lane) * 2;
            asm volatile("ld.shared.v2.b32 {%0,%1}, [%2];"
                         : "=r"(bb[j][0]), "=r"(bb[j][1])
                         : "l"(p));
        }
        #pragma unroll
        for (int i = 0; i < 4; i++)
            #pragma unroll
            for (int j = 0; j < 4; j++) {
                asm volatile(
                    "mma.sync.aligned.m16n8k8.row.col.f32.tf32.tf32.f32 "
                    "{%0,%1,%2,%3}, {%4,%5,%6,%7}, {%8,%9}, {%0,%1,%2,%3};"
                    : "+f"(acc[i][j][0]), "+f"(acc[i][j][1]),
                      "+f"(acc[i][j][2]), "+f"(acc[i][j][3])
                    : "r"(a[i][0]), "r"(a[i][1]), "r"(a[i][2]), "r"(a[i][3]),
                      "r"(bb[j][0]), "r"(bb[j][1]));
            }
    }

    // ---- Epilogue: c0,c1 at (g, 2t), (g, 2t+1); c2,c3 at (g+8, ...) ----
    const int g  = lane >> 2;
    const int tt = lane & 3;
    #pragma unroll
    for (int i = 0; i < 4; i++) {
        const int row0 = mBase + mband * 64 + i * 16 + g;
        #pragma unroll
        for (int j = 0; j < 4; j++) {
            const int col = nBase + nband * 32 + j * 8 + tt * 2;
            float2 lo = make_float2(acc[i][j][0], acc[i][j][1]);
            float2 hi = make_float2(acc[i][j][2], acc[i][j][3]);
            *reinterpret_cast<float2*>(Cb + (size_t)row0 * NDIM + col) = lo;
            *reinterpret_cast<float2*>(Cb + (size_t)(row0 + 8) * NDIM + col) = hi;
        }
    }
}

extern "C" void kernel_launch(void* const* d_in, const int* in_sizes, int n_in,
                              void* d_out, int out_size) {
    const float* A = (const float*)d_in[0];
    const float* B = (const float*)d_in[1];
    float* C = (float*)d_out;

    cudaFuncSetAttribute(bmm_tf32_mma_kernel,
                         cudaFuncAttributeMaxDynamicSharedMemorySize, SMEM_BYTES);

    dim3 grid(NDIM / TILE_N, MDIM / TILE_M, BATCH);  // 32 x 32 x 8
    dim3 block(256);
    bmm_tf32_mma_kernel<<<grid, block, SMEM_BYTES>>>(A, B, C);
}

// round 5
// speedup vs baseline: 2.7668x; 1.9080x over previous
#include <cuda_runtime.h>
#include <cstdint>

// Batched NT-GEMM: C[b,i,j] = sum_d A[b,i,d] * B[b,j,d]
// B=8, M=N=4096, K=128, fp32 in/out.  tf32 mma.sync.m16n8k8 path.
//
// 128x128 CTA tile, K streamed in 4 chunks of 32 via cp.async double buffer.
// Smem: raw fp32, XOR-swizzled rows (conflict-free fragment LDS).
// tf32 RNA conversion done in registers after the fragment load.
// 64KB smem/CTA + <=128 regs -> 2 CTAs/SM (16 warps) for latency hiding.

#define BATCH 8
#define MDIM 4096
#define NDIM 4096
#define KDIM 128

#define TILE_M 128
#define TILE_N 128
#define KCHUNK 32
#define NCHUNKS 4

// float offsets inside dynamic smem: per buffer A(128x32) then B(128x32)
#define ABUF(buf) ((buf) * 8192)
#define BBUF(buf) ((buf) * 8192 + 4096)
#define SMEM_BYTES (2 * 8192 * 4)   // 64 KB

__device__ __forceinline__ uint32_t f2tf32(float f) {
    uint32_t u;
    asm("cvt.rna.tf32.f32 %0, %1;" : "=r"(u) : "f"(f));
    return u;
}

__device__ __forceinline__ uint32_t smem_u32(const void* p) {
    uint32_t a;
    asm("{ .reg .u64 t; cvta.to.shared.u64 t, %1; cvt.u32.u64 %0, t; }"
        : "=r"(a) : "l"(p));
    return a;
}

// swizzled float index of logical (row, col) in a 128x32 chunk tile
__device__ __forceinline__ int fidx(int row, int col) {
    return row * 32 + ((((col >> 2) ^ (row & 7)) << 2) | (col & 3));
}

__device__ __forceinline__ void prefetch_chunk(
    const float* __restrict__ Ab, const float* __restrict__ Bb,
    uint32_t smem_base, int buf, int kOff, int tid)
{
    const int c  = tid & 7;          // 16B chunk within row
    const int r0 = tid >> 3;         // 0..31
    #pragma unroll
    for (int it = 0; it < 4; it++) {
        const int row = it * 32 + r0;
        const uint32_t swoff =
            (uint32_t)(row * 32 + ((c ^ (row & 7)) << 2)) * 4u;
        const float* ga = Ab + (size_t)row * KDIM + kOff + c * 4;
        const float* gb = Bb + (size_t)row * KDIM + kOff + c * 4;
        asm volatile("cp.async.cg.shared.global [%0], [%1], 16;"
                     :: "r"(smem_base + (uint32_t)(ABUF(buf) * 4) + swoff),
                        "l"(ga));
        asm volatile("cp.async.cg.shared.global [%0], [%1], 16;"
                     :: "r"(smem_base + (uint32_t)(BBUF(buf) * 4) + swoff),
                        "l"(gb));
    }
}

__global__ __launch_bounds__(256, 2)
void bmm_tf32_pipe_kernel(const float* __restrict__ A,
                          const float* __restrict__ B,
                          float* __restrict__ C) {
    extern __shared__ float sm[];
    const uint32_t smem_base = smem_u32(sm);

    const int tid  = threadIdx.x;
    const int lane = tid & 31;
    const int wid  = tid >> 5;
    const int g    = lane >> 2;      // 0..7
    const int tt   = lane & 3;       // 0..3

    const int b = blockIdx.z;
    const int mBase = blockIdx.y * TILE_M;
    const int nBase = blockIdx.x * TILE_N;

    const float* Ab = A + (size_t)b * MDIM * KDIM + (size_t)mBase * KDIM;
    const float* Bb = B + (size_t)b * NDIM * KDIM + (size_t)nBase * KDIM;
    float* Cb = C + (size_t)b * MDIM * NDIM;

    const int mband = wid >> 2;      // 0..1  (64-row band)
    const int nband = wid & 3;       // 0..3  (32-col band)

    float acc[4][4][4];
    #pragma unroll
    for (int i = 0; i < 4; i++)
        #pragma unroll
        for (int j = 0; j < 4; j++)
            #pragma unroll
            for (int r = 0; r < 4; r++)
                acc[i][j][r] = 0.0f;

    // Prime the pipeline: chunks 0 and 1
    prefetch_chunk(Ab, Bb, smem_base, 0, 0, tid);
    asm volatile("cp.async.commit_group;" ::: "memory");
    prefetch_chunk(Ab, Bb, smem_base, 1, KCHUNK, tid);
    asm volatile("cp.async.commit_group;" ::: "memory");

    #pragma unroll
    for (int ch = 0; ch < NCHUNKS; ch++) {
        if (ch < NCHUNKS - 1) {
            asm volatile("cp.async.wait_group 1;" ::: "memory");
        } else {
            asm volatile("cp.async.wait_group 0;" ::: "memory");
        }
        __syncthreads();

        const float* As = sm + ABUF(ch & 1);
        const float* Bs = sm + BBUF(ch & 1);

        #pragma unroll
        for (int kt = 0; kt < 4; kt++) {
            const int ko = kt * 8;
            uint32_t a[4][4], bf[4][2];
            #pragma unroll
            for (int i = 0; i < 4; i++) {
                const int r0 = mband * 64 + i * 16 + g;
                a[i][0] = f2tf32(As[fidx(r0,     ko + tt)]);
                a[i][1] = f2tf32(As[fidx(r0 + 8, ko + tt)]);
                a[i][2] = f2tf32(As[fidx(r0,     ko + tt + 4)]);
                a[i][3] = f2tf32(As[fidx(r0 + 8, ko + tt + 4)]);
            }
            #pragma unroll
            for (int j = 0; j < 4; j++) {
                const int n0 = nband * 32 + j * 8 + g;
                bf[j][0] = f2tf32(Bs[fidx(n0, ko + tt)]);
                bf[j][1] = f2tf32(Bs[fidx(n0, ko + tt + 4)]);
            }
            #pragma unroll
            for (int i = 0; i < 4; i++)
                #pragma unroll
                for (int j = 0; j < 4; j++) {
                    asm volatile(
                        "mma.sync.aligned.m16n8k8.row.col.f32.tf32.tf32.f32 "
                        "{%0,%1,%2,%3}, {%4,%5,%6,%7}, {%8,%9}, {%0,%1,%2,%3};"
                        : "+f"(acc[i][j][0]), "+f"(acc[i][j][1]),
                          "+f"(acc[i][j][2]), "+f"(acc[i][j][3])
                        : "r"(a[i][0]), "r"(a[i][1]),
                          "r"(a[i][2]), "r"(a[i][3]),
                          "r"(bf[j][0]), "r"(bf[j][1]));
                }
        }

        if (ch + 2 < NCHUNKS) {
            __syncthreads();   // all warps done reading this buffer
            prefetch_chunk(Ab, Bb, smem_base, ch & 1, (ch + 2) * KCHUNK, tid);
            asm volatile("cp.async.commit_group;" ::: "memory");
        }
    }

    // Epilogue: c0,c1 -> (row g, cols 2t,2t+1); c2,c3 -> (row g+8, ...)
    #pragma unroll
    for (int i = 0; i < 4; i++) {
        const int row0 = mBase + mband * 64 + i * 16 + g;
        #pragma unroll
        for (int j = 0; j < 4; j++) {
            const int col = nBase + nband * 32 + j * 8 + tt * 2;
            float2 lo = make_float2(acc[i][j][0], acc[i][j][1]);
            float2 hi = make_float2(acc[i][j][2], acc[i][j][3]);
            *reinterpret_cast<float2*>(Cb + (size_t)row0 * NDIM + col) = lo;
            *reinterpret_cast<float2*>(Cb + (size_t)(row0 + 8) * NDIM + col) = hi;
        }
    }
}

extern "C" void kernel_launch(void* const* d_in, const int* in_sizes, int n_in,
                              void* d_out, int out_size) {
    const float* A = (const float*)d_in[0];
    const float* B = (const float*)d_in[1];
    float* C = (float*)d_out;

    cudaFuncSetAttribute(bmm_tf32_pipe_kernel,
                         cudaFuncAttributeMaxDynamicSharedMemorySize, SMEM_BYTES);

    dim3 grid(NDIM / TILE_N, MDIM / TILE_M, BATCH);  // 32 x 32 x 8
    dim3 block(256);
    bmm_tf32_pipe_kernel<<<grid, block, SMEM_BYTES>>>(A, B, C);
}

// round 7
// speedup vs baseline: 3.8585x; 1.3946x over previous
#include <cuda_runtime.h>
#include <cstdint>

// Batched NT-GEMM: C[b,i,j] = sum_d A[b,i,d] * B[b,j,d]
// B=8, M=N=4096, K=128, fp32 in/out.
//
// Two-phase: (1) prepass converts A,B to tf32 (RNA) into __device__ scratch in
// FRAGMENT-MAJOR layout for mma.sync.m16n8k8; (2) main GEMM cp.asyncs those
// contiguous fragment blocks and runs ld.shared.v4/v2 + mma only (no cvt).

#define BATCH 8
#define MDIM 4096
#define NDIM 4096
#define KDIM 128

#define TILE_M 128
#define TILE_N 128
#define NCHUNKS 4          // K chunks of 32 (4 kt-groups of 8)

// Fragment-major scratch:
// Atf: [b][M128(32)][kt(16)][mt(8)][lane(32)][r(4)]   (16.8 MB)
// Btf: [b][N128(32)][kt(16)][nt(16)][lane(32)][r(2)]  (16.8 MB)
__device__ float g_Atf[(size_t)BATCH * MDIM * KDIM];
__device__ float g_Btf[(size_t)BATCH * NDIM * KDIM];

// Smem per buffer: A 4096 floats [kt4][mt8][lane32][r4], B 4096 floats
// [kt4][nt16][lane32][r2].  2 buffers x 32KB = 64KB.
#define BUF_FLOATS 8192
#define SMEM_BYTES (2 * BUF_FLOATS * 4)

__device__ __forceinline__ float f2tf32f(float f) {
    uint32_t u;
    asm("cvt.rna.tf32.f32 %0, %1;" : "=r"(u) : "f"(f));
    return __uint_as_float(u);
}

__device__ __forceinline__ uint32_t smem_u32(const void* p) {
    uint32_t a;
    asm("{ .reg .u64 t; cvta.to.shared.u64 t, %1; cvt.u32.u64 %0, t; }"
        : "=r"(a) : "l"(p));
    return a;
}

// ---------------- Prepass: A -> fragment-major tf32 ----------------
// One thread per output float4 = (b, M128, kt, mt, lane).
__global__ __launch_bounds__(256)
void prep_a_kernel(const float* __restrict__ A) {
    const int id   = blockIdx.x * 256 + threadIdx.x;   // 0 .. 2^20-1
    const int lane = id & 31;
    const int mt   = (id >> 5) & 7;
    const int kt   = (id >> 8) & 15;
    const int M    = (id >> 12) & 31;
    const int b    = id >> 17;

    const int g  = lane >> 2;
    const int tt = lane & 3;
    const int m0 = M * 128 + mt * 16 + g;
    const int k0 = kt * 8 + tt;

    const float* src = A + ((size_t)b * MDIM + m0) * KDIM;
    float4 v;
    v.x = f2tf32f(src[k0]);                       // (g,   tt)
    v.y = f2tf32f(src[8 * KDIM + k0]);            // (g+8, tt)
    v.z = f2tf32f(src[k0 + 4]);                   // (g,   tt+4)
    v.w = f2tf32f(src[8 * KDIM + k0 + 4]);        // (g+8, tt+4)
    *reinterpret_cast<float4*>(g_Atf + (size_t)id * 4) = v;
}

// One thread per output float2 = (b, N128, kt, nt, lane).
__global__ __launch_bounds__(256)
void prep_b_kernel(const float* __restrict__ B) {
    const int id   = blockIdx.x * 256 + threadIdx.x;   // 0 .. 2^21-1
    const int lane = id & 31;
    const int nt   = (id >> 5) & 15;
    const int kt   = (id >> 9) & 15;
    const int N    = (id >> 13) & 31;
    const int b    = id >> 18;

    const int g  = lane >> 2;
    const int tt = lane & 3;
    const int n0 = N * 128 + nt * 8 + g;
    const int k0 = kt * 8 + tt;

    const float* src = B + ((size_t)b * NDIM + n0) * KDIM;
    float2 v;
    v.x = f2tf32f(src[k0]);
    v.y = f2tf32f(src[k0 + 4]);
    *reinterpret_cast<float2*>(g_Btf + (size_t)id * 2) = v;
}

// ---------------- Main GEMM ----------------
__global__ __launch_bounds__(256, 2)
void bmm_tf32_frag_kernel(float* __restrict__ C) {
    extern __shared__ float sm[];
    const uint32_t smem_base = smem_u32(sm);

    const int tid  = threadIdx.x;
    const int lane = tid & 31;
    const int wid  = tid >> 5;
    const int g    = lane >> 2;
    const int tt   = lane & 3;

    const int b  = blockIdx.z;
    const int by = blockIdx.y;          // M128 tile
    const int bx = blockIdx.x;          // N128 tile

    const float* srcA = g_Atf + (size_t)((b * 32 + by) * 16) * 1024;
    const float* srcB = g_Btf + (size_t)((b * 32 + bx) * 16) * 1024;
    float* Cb = C + (size_t)b * MDIM * NDIM;

    const int mband = wid >> 2;         // 0..1
    const int nband = wid & 3;          // 0..3

    float acc[4][4][4];
    #pragma unroll
    for (int i = 0; i < 4; i++)
        #pragma unroll
        for (int j = 0; j < 4; j++)
            #pragma unroll
            for (int r = 0; r < 4; r++)
                acc[i][j][r] = 0.0f;

    // prefetch helper inlined: chunk c -> buffer buf
    auto prefetch = [&](int buf, int c) {
        const float* ca = srcA + c * 4096;
        const float* cb = srcB + c * 4096;
        const uint32_t da = smem_base + (uint32_t)buf * (BUF_FLOATS * 4);
        const uint32_t db = da + 16384;
        #pragma unroll
        for (int i = 0; i < 4; i++) {
            const int o = tid + i * 256;      // 16B chunk index
            asm volatile("cp.async.cg.shared.global [%0], [%1], 16;"
                         :: "r"(da + (uint32_t)o * 16), "l"(ca + o * 4));
            asm volatile("cp.async.cg.shared.global [%0], [%1], 16;"
                         :: "r"(db + (uint32_t)o * 16), "l"(cb + o * 4));
        }
    };

    prefetch(0, 0);
    asm volatile("cp.async.commit_group;" ::: "memory");
    prefetch(1, 1);
    asm volatile("cp.async.commit_group;" ::: "memory");

    #pragma unroll
    for (int ch = 0; ch < NCHUNKS; ch++) {
        if (ch < NCHUNKS - 1)
            asm volatile("cp.async.wait_group 1;" ::: "memory");
        else
            asm volatile("cp.async.wait_group 0;" ::: "memory");
        __syncthreads();

        const float* As = sm + (ch & 1) * BUF_FLOATS;          // [kt][mt][lane][4]
        const float* Bs = As + 4096;                           // [kt][nt][lane][2]

        #pragma unroll
        for (int kt = 0; kt < 4; kt++) {
            uint32_t a[4][4], bf[4][2];
            #pragma unroll
            for (int i = 0; i < 4; i++) {
                const float* p = As + ((kt * 8 + mband * 4 + i) * 32 + lane) * 4;
                asm volatile("ld.shared.v4.b32 {%0,%1,%2,%3}, [%4];"
                             : "=r"(a[i][0]), "=r"(a[i][1]),
                               "=r"(a[i][2]), "=r"(a[i][3])
                             : "l"(p));
            }
            #pragma unroll
            for (int j = 0; j < 4; j++) {
                const float* p = Bs + ((kt * 16 + nband * 4 + j) * 32 + lane) * 2;
                asm volatile("ld.shared.v2.b32 {%0,%1}, [%2];"
                             : "=r"(bf[j][0]), "=r"(bf[j][1])
                             : "l"(p));
            }
            #pragma unroll
            for (int i = 0; i < 4; i++)
                #pragma unroll
                for (int j = 0; j < 4; j++) {
                    asm volatile(
                        "mma.sync.aligned.m16n8k8.row.col.f32.tf32.tf32.f32 "
                        "{%0,%1,%2,%3}, {%4,%5,%6,%7}, {%8,%9}, {%0,%1,%2,%3};"
                        : "+f"(acc[i][j][0]), "+f"(acc[i][j][1]),
                          "+f"(acc[i][j][2]), "+f"(acc[i][j][3])
                        : "r"(a[i][0]), "r"(a[i][1]),
                          "r"(a[i][2]), "r"(a[i][3]),
                          "r"(bf[j][0]), "r"(bf[j][1]));
                }
        }

        if (ch + 2 < NCHUNKS) {
            __syncthreads();
            prefetch(ch & 1, ch + 2);
            asm volatile("cp.async.commit_group;" ::: "memory");
        }
    }

    // Epilogue
    const int mBase = by * TILE_M;
    const int nBase = bx * TILE_N;
    #pragma unroll
    for (int i = 0; i < 4; i++) {
        const int row0 = mBase + mband * 64 + i * 16 + g;
        #pragma unroll
        for (int j = 0; j < 4; j++) {
            const int col = nBase + nband * 32 + j * 8 + tt * 2;
            float2 lo = make_float2(acc[i][j][0], acc[i][j][1]);
            float2 hi = make_float2(acc[i][j][2], acc[i][j][3]);
            *reinterpret_cast<float2*>(Cb + (size_t)row0 * NDIM + col) = lo;
            *reinterpret_cast<float2*>(Cb + (size_t)(row0 + 8) * NDIM + col) = hi;
        }
    }
}

extern "C" void kernel_launch(void* const* d_in, const int* in_sizes, int n_in,
                              void* d_out, int out_size) {
    const float* A = (const float*)d_in[0];
    const float* B = (const float*)d_in[1];
    float* C = (float*)d_out;

    cudaFuncSetAttribute(bmm_tf32_frag_kernel,
                         cudaFuncAttributeMaxDynamicSharedMemorySize, SMEM_BYTES);

    prep_a_kernel<<<4096, 256>>>(A);     // 2^20 threads
    prep_b_kernel<<<8192, 256>>>(B);     // 2^21 threads

    dim3 grid(NDIM / TILE_N, MDIM / TILE_M, BATCH);  // 32 x 32 x 8
    bmm_tf32_frag_kernel<<<grid, 256, SMEM_BYTES>>>(C);
}